// round 12
// baseline (speedup 1.0000x reference)
#include <cuda_runtime.h>
#include <cuda_fp16.h>
#include <cstdint>

#define B_ 32
#define S_ 64
#define H_ 8
#define E_ 1024
#define HE_ 8192
#define M_ 2048
#define NSPLIT 4
#define KSPL (HE_ / NSPLIT)   // 2048

// ---------------- scratch (__device__ globals) ------------------------------
__device__ __half g_qh[B_ * H_ * S_ * E_];
__device__ __half g_kh[B_ * H_ * S_ * E_];
__device__ __half g_vh[B_ * H_ * S_ * E_];
__device__ __half g_y[M_ * HE_];
__device__ __half g_xh[M_ * E_];
__device__ __half g_wqkv[3 * HE_ * E_];
__device__ __half g_woh[E_ * HE_];
__device__ __half g_p[B_ * H_ * S_ * S_];
__device__ float  g_part[NSPLIT * M_ * E_];

// ---------------- helpers ---------------------------------------------------
__device__ __forceinline__ uint32_t s2u(const void* p) {
    uint32_t a;
    asm("{ .reg .u64 t; cvta.to.shared.u64 t, %1; cvt.u32.u64 %0, t; }"
        : "=r"(a) : "l"(p));
    return a;
}

__device__ __forceinline__ void cpasync16(uint32_t dst, const void* src) {
    asm volatile("cp.async.cg.shared.global [%0], [%1], 16;" :: "r"(dst), "l"(src));
}

__device__ __forceinline__ uint32_t packh2(float a, float b) {
    __half2 h = __floats2half2_rn(a, b);
    return *reinterpret_cast<uint32_t*>(&h);
}

__device__ __forceinline__ void ldmx4(uint32_t* r, uint32_t addr) {
    asm volatile("ldmatrix.sync.aligned.m8n8.x4.shared.b16 {%0,%1,%2,%3}, [%4];"
                 : "=r"(r[0]), "=r"(r[1]), "=r"(r[2]), "=r"(r[3]) : "r"(addr));
}

__device__ __forceinline__ void ldmx4t(uint32_t* r, uint32_t addr) {
    asm volatile("ldmatrix.sync.aligned.m8n8.x4.trans.shared.b16 {%0,%1,%2,%3}, [%4];"
                 : "=r"(r[0]), "=r"(r[1]), "=r"(r[2]), "=r"(r[3]) : "r"(addr));
}

__device__ __forceinline__ void mma_f16(float* d, const uint32_t* a,
                                        const uint32_t* b) {
    asm volatile(
        "mma.sync.aligned.m16n8k16.row.col.f32.f16.f16.f32 "
        "{%0,%1,%2,%3}, {%4,%5,%6,%7}, {%8,%9}, {%0,%1,%2,%3};"
        : "+f"(d[0]), "+f"(d[1]), "+f"(d[2]), "+f"(d[3])
        : "r"(a[0]), "r"(a[1]), "r"(a[2]), "r"(a[3]), "r"(b[0]), "r"(b[1]));
}

// ---------------- fp32->fp16 conversion kernels (32B/thread) ----------------
#define N4X  (M_ * E_ / 4)
#define N4W  (HE_ * E_ / 4)
#define N8X  (N4X / 2)
#define N8W  (N4W / 2)

__global__ void __launch_bounds__(256) cvt_xq_kernel(
    const float4* __restrict__ x, const float4* __restrict__ wq,
    uint4* __restrict__ xh, uint4* __restrict__ wqkvh)
{
    int i = blockIdx.x * blockDim.x + threadIdx.x;
    const float4* src;
    uint4* dst;
    if (i < N8X)            { src = x + i * 2;               dst = xh + i; }
    else if (i < N8X + N8W) { int j = i - N8X; src = wq + j * 2; dst = wqkvh + j; }
    else return;
    float4 v0 = src[0];
    float4 v1 = src[1];
    uint4 o;
    o.x = packh2(v0.x, v0.y);
    o.y = packh2(v0.z, v0.w);
    o.z = packh2(v1.x, v1.y);
    o.w = packh2(v1.z, v1.w);
    *dst = o;
}

__global__ void __launch_bounds__(256) cvt_w2_kernel(
    const float4* __restrict__ wk, const float4* __restrict__ wv,
    uint4* __restrict__ wqkvh)
{
    int i = blockIdx.x * blockDim.x + threadIdx.x;
    const float4* src;
    uint4* dst;
    if (i < N8W)            { src = wk + i * 2;               dst = wqkvh + N8W + i; }
    else if (i < 2 * N8W)   { int j = i - N8W; src = wv + j * 2; dst = wqkvh + 2 * N8W + j; }
    else return;
    float4 v0 = src[0];
    float4 v1 = src[1];
    uint4 o;
    o.x = packh2(v0.x, v0.y);
    o.y = packh2(v0.z, v0.w);
    o.z = packh2(v1.x, v1.y);
    o.w = packh2(v1.z, v1.w);
    *dst = o;
}

__global__ void __launch_bounds__(256) cvt_wo_kernel(
    const float4* __restrict__ wo, uint4* __restrict__ woh)
{
    int i = blockIdx.x * blockDim.x + threadIdx.x;
    if (i >= N8W) return;
    float4 v0 = wo[i * 2];
    float4 v1 = wo[i * 2 + 1];
    uint4 o;
    o.x = packh2(v0.x, v0.y);
    o.y = packh2(v0.z, v0.w);
    o.z = packh2(v1.x, v1.y);
    o.w = packh2(v1.z, v1.w);
    woh[i] = o;
}

// ---------------- fp16 tensor-core GEMM (NT) — R8 config --------------------
// CTA tile 128x128x32, 128 threads, 4 warps (64x64 warp tile), 4-stage
// cp.async, single sync per iter, 64B smem rows, chunk ^= (row>>1)&3.
// MODE 0 (projection, fp16 out): out[((b*H+h)*S+s)*E+e] = acc*mask*scale.
// MODE 2 (split-K partial): fp32 partial into slice blockIdx.z.
#define TSTG 8192
#define NSTAGE 4

template<int KTOT, int KITER, int MODE>
__global__ void __launch_bounds__(128) gemm_f16(
    const __half* __restrict__ A, const __half* __restrict__ Wt,
    const float* __restrict__ mask, void* __restrict__ p0, float scale)
{
    constexpr int NIT = KITER / 32;
    extern __shared__ __align__(16) char sm[];
    const uint32_t sAu = s2u(sm);
    const uint32_t sBu = sAu + NSTAGE * TSTG;

    const int tid = threadIdx.x;
    const int wid = tid >> 5, lane = tid & 31;
    const int wm = wid & 1;          // 64-row group
    const int wn = wid >> 1;         // 64-col group
    const int lr = lane >> 2;
    const int lc = lane & 3;
    const int m0 = blockIdx.y * 128;
    const int n0 = blockIdx.x * 128;
    const int k0 = (MODE == 2) ? blockIdx.z * KITER : 0;

    const int ldrow = tid >> 2;      // 0..31
    const int ldch = tid & 3;
    const __half* Abase = A + (size_t)(m0 + ldrow) * KTOT + k0 + ldch * 8;
    const __half* Bbase = Wt + (size_t)(n0 + ldrow) * KTOT + k0 + ldch * 8;

    auto load_stage = [&](int s, int kt) {
#pragma unroll
        for (int p = 0; p < 4; p++) {
            int r = ldrow + p * 32;
            uint32_t doff = (uint32_t)(r * 64 + ((ldch ^ ((r >> 1) & 3)) << 4));
            cpasync16(sAu + s * TSTG + doff, Abase + (size_t)p * 32 * KTOT + kt * 32);
            cpasync16(sBu + s * TSTG + doff, Bbase + (size_t)p * 32 * KTOT + kt * 32);
        }
        asm volatile("cp.async.commit_group;" ::: "memory");
    };

    load_stage(0, 0);
    load_stage(1, 1);
    load_stage(2, 2);

    float acc[4][8][4];              // [mt][nt][frag] = 128 regs
#pragma unroll
    for (int i = 0; i < 4; i++)
#pragma unroll
        for (int j = 0; j < 8; j++)
#pragma unroll
            for (int f = 0; f < 4; f++) acc[i][j][f] = 0.0f;

    const int arow0 = wm * 64 + (lane & 15);
    const int acs = lane >> 4;
    const int midx = lane >> 3;
    const int brow0 = wn * 64 + ((midx >> 1) << 3) + (lane & 7);
    const int bcs = midx & 1;

    for (int j = 0; j < NIT; j++) {
        const int s = j & (NSTAGE - 1);
        if (j < NIT - 2)       asm volatile("cp.async.wait_group 2;" ::: "memory");
        else if (j == NIT - 2) asm volatile("cp.async.wait_group 1;" ::: "memory");
        else                   asm volatile("cp.async.wait_group 0;" ::: "memory");
        __syncthreads();
        if (j + 3 < NIT) load_stage((j + 3) & (NSTAGE - 1), j + 3);

        const uint32_t As = sAu + s * TSTG;
        const uint32_t Bs = sBu + s * TSTG;

#pragma unroll
        for (int ks = 0; ks < 2; ks++) {
            uint32_t bf[4][4];
#pragma unroll
            for (int ntp = 0; ntp < 4; ntp++) {
                int r = brow0 + ntp * 16;
                int ch = (ks * 2 + bcs) ^ ((r >> 1) & 3);
                ldmx4(bf[ntp], Bs + (uint32_t)(r * 64 + (ch << 4)));
            }
#pragma unroll
            for (int mt = 0; mt < 4; mt++) {
                int r = arow0 + mt * 16;
                int ch = (ks * 2 + acs) ^ ((r >> 1) & 3);
                uint32_t af[4];
                ldmx4(af, As + (uint32_t)(r * 64 + (ch << 4)));
#pragma unroll
                for (int nt = 0; nt < 8; nt++)
                    mma_f16(acc[mt][nt], af, bf[nt >> 1] + (nt & 1) * 2);
            }
        }
    }

    // ---- epilogue ----
#pragma unroll
    for (int mt = 0; mt < 4; mt++) {
#pragma unroll
        for (int half = 0; half < 2; half++) {
            const int m = m0 + wm * 64 + mt * 16 + half * 8 + lr;
            const int b = m >> 6;
#pragma unroll
            for (int nt = 0; nt < 8; nt++) {
                const int nrel = wn * 64 + nt * 8 + lc * 2;
                float v0 = acc[mt][nt][half * 2 + 0];
                float v1 = acc[mt][nt][half * 2 + 1];
                if (MODE == 0) {
                    const int n = n0 + nrel;
                    const int h = n >> 10;
                    const int e = n & 1023;
                    const int sidx = m & 63;
                    const float* mp = mask + (size_t)b * E_ + e;
                    uint32_t o = packh2(v0 * mp[0] * scale, v1 * mp[1] * scale);
                    *(uint32_t*)((__half*)p0 +
                        ((size_t)((b * H_ + h) * S_ + sidx)) * E_ + e) = o;
                } else {
                    const int n = n0 + nrel;
                    float* outp = (float*)p0 + (size_t)blockIdx.z * M_ * E_;
                    float2 o; o.x = v0; o.y = v1;
                    *(float2*)(outp + (size_t)m * E_ + n) = o;
                }
            }
        }
    }
}

// ---------------- split-K reduce: out = (sum parts + bias) * mask -----------
__global__ void __launch_bounds__(256) reduce_kernel(
    const float4* __restrict__ part, const float* __restrict__ bias,
    const float* __restrict__ mask, float4* __restrict__ out)
{
    const int i = blockIdx.x * blockDim.x + threadIdx.x;
    if (i >= M_ * E_ / 4) return;
    const int idx = i * 4;
    const int m = idx >> 10;
    const int n = idx & 1023;
    const int b = m >> 6;

    float4 s = part[i];
    float4 p1 = part[i + (M_ * E_ / 4)];
    float4 p2 = part[i + 2 * (M_ * E_ / 4)];
    float4 p3 = part[i + 3 * (M_ * E_ / 4)];
    s.x += p1.x + p2.x + p3.x;
    s.y += p1.y + p2.y + p3.y;
    s.z += p1.z + p2.z + p3.z;
    s.w += p1.w + p2.w + p3.w;

    float4 bv = *(const float4*)(bias + n);
    float4 mv = *(const float4*)(mask + (size_t)b * E_ + n);
    float4 o;
    o.x = (s.x + bv.x) * mv.x;
    o.y = (s.y + bv.y) * mv.y;
    o.z = (s.z + bv.z) * mv.z;
    o.w = (s.w + bv.w) * mv.w;
    out[i] = o;
}

// ---------------- attention phase 1: logits + softmax -> P (fp16, global) ---
#define LOG_SMEM 54272

__global__ void __launch_bounds__(256) attn_logits_kernel(
    const __half* __restrict__ q, const __half* __restrict__ k,
    __half* __restrict__ p)
{
    const int h = blockIdx.x;
    const int b = blockIdx.y;
    const __half* qb = q + (size_t)((b * H_ + h) * S_) * E_;
    const __half* kb = k + (size_t)((b * H_ + h) * S_) * E_;
    __half* pp = p + (size_t)(b * H_ + h) * (S_ * S_);

    extern __shared__ __align__(16) char sm[];
    const uint32_t sb = s2u(sm);
    const uint32_t sQ[2] = { sb, sb + 9216 };
    const uint32_t sK[2] = { sb + 18432, sb + 27648 };
    float* sL = (float*)(sm + 36864);

    const int tid = threadIdx.x;
    const int wid = tid >> 5, lane = tid & 31;
    const int ldr = tid >> 2;
    const int ldc = tid & 3;

    auto loadQK = [&](int s, int kc) {
        const __half* qs = qb + (size_t)ldr * E_ + kc * 64 + ldc * 8;
        const __half* ks = kb + (size_t)ldr * E_ + kc * 64 + ldc * 8;
        uint32_t d = (uint32_t)(ldr * 144 + ldc * 16);
        cpasync16(sQ[s] + d, qs);
        cpasync16(sQ[s] + d + 64, qs + 32);
        cpasync16(sK[s] + d, ks);
        cpasync16(sK[s] + d + 64, ks + 32);
        asm volatile("cp.async.commit_group;" ::: "memory");
    };

    loadQK(0, 0);
    loadQK(1, 1);

    const int wm = wid & 3;
    const int wn = wid >> 2;
    const int arow = wm * 16 + (lane & 15);
    const int acs = lane >> 4;
    const int midx = lane >> 3;
    const int brow = wn * 32 + ((midx >> 1) << 3) + (lane & 7);
    const int bcs = midx & 1;

    float acc[4][4];
#pragma unroll
    for (int i = 0; i < 4; i++)
#pragma unroll
        for (int f = 0; f < 4; f++) acc[i][f] = 0.0f;

    for (int c = 0; c < 16; c++) {
        const int cur = c & 1;
        asm volatile("cp.async.wait_group 1;" ::: "memory");
        __syncthreads();
#pragma unroll
        for (int ks = 0; ks < 4; ks++) {
            uint32_t af[4];
            ldmx4(af, sQ[cur] + (uint32_t)(arow * 144 + ks * 32 + acs * 16));
            uint32_t bf[2][4];
#pragma unroll
            for (int ntp = 0; ntp < 2; ntp++)
                ldmx4(bf[ntp], sK[cur] + (uint32_t)((brow + ntp * 16) * 144 +
                                                    ks * 32 + bcs * 16));
#pragma unroll
            for (int nt = 0; nt < 4; nt++)
                mma_f16(acc[nt], af, bf[nt >> 1] + (nt & 1) * 2);
        }
        __syncthreads();
        if (c + 2 < 16) loadQK(cur, c + 2);
        else asm volatile("cp.async.commit_group;" ::: "memory");
    }

    {
        const int r0 = wm * 16 + (lane >> 2);
        const int cbase = wn * 32 + (lane & 3) * 2;
#pragma unroll
        for (int nt = 0; nt < 4; nt++) {
            sL[(r0)     * 68 + cbase + nt * 8]     = acc[nt][0];
            sL[(r0)     * 68 + cbase + nt * 8 + 1] = acc[nt][1];
            sL[(r0 + 8) * 68 + cbase + nt * 8]     = acc[nt][2];
            sL[(r0 + 8) * 68 + cbase + nt * 8 + 1] = acc[nt][3];
        }
    }
    __syncthreads();

    {
        const int row = tid >> 2;
        const int cb = (tid & 3) * 16;
        float mx = -1e30f;
#pragma unroll
        for (int c = 0; c < 16; c++) mx = fmaxf(mx, sL[row * 68 + cb + c]);
        mx = fmaxf(mx, __shfl_xor_sync(0xffffffffu, mx, 1));
        mx = fmaxf(mx, __shfl_xor_sync(0xffffffffu, mx, 2));
        float ev[16];
        float sum = 0.0f;
#pragma unroll
        for (int c = 0; c < 16; c++) {
            ev[c] = __expf(sL[row * 68 + cb + c] - mx);
            sum += ev[c];
        }
        sum += __shfl_xor_sync(0xffffffffu, sum, 1);
        sum += __shfl_xor_sync(0xffffffffu, sum, 2);
        float inv = 1.0f / sum;
#pragma unroll
        for (int c = 0; c < 8; c++) {
            uint32_t pk = packh2(ev[c * 2] * inv, ev[c * 2 + 1] * inv);
            *(uint32_t*)(pp + row * 64 + cb + c * 2) = pk;
        }
    }
}

// ---------------- attention phase 2: y = P @ V ------------------------------
#define AV_SMEM 44032

__global__ void __launch_bounds__(256) attn_av_kernel(
    const __half* __restrict__ p, const __half* __restrict__ v,
    __half* __restrict__ y)
{
    const int h = blockIdx.x;
    const int b = blockIdx.y;
    const __half* pb = p + (size_t)(b * H_ + h) * (S_ * S_);
    const __half* vb = v + (size_t)((b * H_ + h) * S_) * E_;
    __half* yb = y + (size_t)b * S_ * HE_ + h * E_;

    extern __shared__ __align__(16) char sm[];
    const uint32_t sb = s2u(sm);
    const uint32_t sP = sb;                         // 64 rows x 144B
    const uint32_t sV[2] = { sb + 9216, sb + 26624 };

    const int tid = threadIdx.x;
    const int wid = tid >> 5, lane = tid & 31;
    const int ldr = tid >> 2;
    const int ldc = tid & 3;
    const int acs = lane >> 4;

    // load P (64x64 fp16) into sP
    {
        const __half* ps = pb + ldr * 64 + ldc * 8;
        uint32_t d = (uint32_t)(ldr * 144 + ldc * 16);
        cpasync16(sP + d, ps);
        cpasync16(sP + d + 64, ps + 32);
        asm volatile("cp.async.commit_group;" ::: "memory");
    }

    auto loadV = [&](int s, int ec) {
        const __half* vs = vb + (size_t)ldr * E_ + ec * 128 + ldc * 8;
        uint32_t d = (uint32_t)(ldr * 272 + ldc * 16);
#pragma unroll
        for (int jj = 0; jj < 4; jj++)
            cpasync16(sV[s] + d + jj * 64, vs + jj * 32);
        asm volatile("cp.async.commit_group;" ::: "memory");
    };

    loadV(0, 0);
    loadV(1, 1);

    const int wm2 = wid & 1;
    const int wn2 = wid >> 1;
    const int prow0 = wm2 * 32 + (lane & 15);
    const int vs0 = ((lane >> 3) & 1) * 8 + (lane & 7);
    const int ve0 = wn2 * 32 + (lane >> 4) * 8;

    for (int ec = 0; ec < 8; ec++) {
        const int cur = ec & 1;
        asm volatile("cp.async.wait_group 1;" ::: "memory");
        __syncthreads();

        float acc2[2][4][4];
#pragma unroll
        for (int i = 0; i < 2; i++)
#pragma unroll
            for (int j = 0; j < 4; j++)
#pragma unroll
                for (int f = 0; f < 4; f++) acc2[i][j][f] = 0.0f;

#pragma unroll
        for (int ks = 0; ks < 4; ks++) {
            uint32_t bf[2][4];
#pragma unroll
            for (int ntp = 0; ntp < 2; ntp++)
                ldmx4t(bf[ntp], sV[cur] + (uint32_t)((ks * 16 + vs0) * 272 +
                                                     (ve0 + ntp * 16) * 2));
#pragma unroll
            for (int mt = 0; mt < 2; mt++) {
                uint32_t af[4];
                ldmx4(af, sP + (uint32_t)((prow0 + mt * 16) * 144 +
                                          ks * 32 + acs * 16));
#pragma unroll
                for (int nt = 0; nt < 4; nt++)
                    mma_f16(acc2[mt][nt], af, bf[nt >> 1] + (nt & 1) * 2);
            }
        }

#pragma unroll
        for (int mt = 0; mt < 2; mt++) {
#pragma unroll
            for (int half = 0; half < 2; half++) {
                const int row = wm2 * 32 + mt * 16 + half * 8 + (lane >> 2);
#pragma unroll
                for (int nt = 0; nt < 4; nt++) {
                    const int col = ec * 128 + wn2 * 32 + nt * 8 + (lane & 3) * 2;
                    uint32_t o = packh2(acc2[mt][nt][half * 2],
                                        acc2[mt][nt][half * 2 + 1]);
                    *(uint32_t*)(yb + (size_t)row * HE_ + col) = o;
                }
            }
        }

        __syncthreads();
        if (ec + 2 < 8) loadV(cur, ec + 2);
        else asm volatile("cp.async.commit_group;" ::: "memory");
    }
}

// ---------------------------------------------------------------------------
extern "C" void kernel_launch(void* const* d_in, const int* in_sizes, int n_in,
                              void* d_out, int out_size)
{
    const float* x    = (const float*)d_in[0];
    const float* mask = (const float*)d_in[1];
    const float* Wq   = (const float*)d_in[2];
    const float* Wk   = (const float*)d_in[3];
    const float* Wv   = (const float*)d_in[4];
    const float* Wo   = (const float*)d_in[5];
    const float* bo   = (const float*)d_in[6];
    float* out = (float*)d_out;

    __half *qh, *kh, *vh, *yh, *xh, *wqkv, *woh, *ph;
    float *part;
    cudaGetSymbolAddress((void**)&qh, g_qh);
    cudaGetSymbolAddress((void**)&kh, g_kh);
    cudaGetSymbolAddress((void**)&vh, g_vh);
    cudaGetSymbolAddress((void**)&yh, g_y);
    cudaGetSymbolAddress((void**)&xh, g_xh);
    cudaGetSymbolAddress((void**)&wqkv, g_wqkv);
    cudaGetSymbolAddress((void**)&woh, g_woh);
    cudaGetSymbolAddress((void**)&ph, g_p);
    cudaGetSymbolAddress((void**)&part, g_part);

    const int SMEM = 2 * NSTAGE * TSTG;   // 65536
    static cudaStream_t s2 = nullptr;
    static cudaEvent_t evFork = nullptr, evKV = nullptr, evWo = nullptr;
    static cudaEvent_t evK2 = nullptr, evLog = nullptr;
    if (s2 == nullptr) {
        // first call is the uncaptured correctness run: safe to create here
        cudaStreamCreateWithFlags(&s2, cudaStreamNonBlocking);
        cudaEventCreateWithFlags(&evFork, cudaEventDisableTiming);
        cudaEventCreateWithFlags(&evKV, cudaEventDisableTiming);
        cudaEventCreateWithFlags(&evWo, cudaEventDisableTiming);
        cudaEventCreateWithFlags(&evK2, cudaEventDisableTiming);
        cudaEventCreateWithFlags(&evLog, cudaEventDisableTiming);
        cudaFuncSetAttribute((const void*)gemm_f16<E_, E_, 0>,
                             cudaFuncAttributeMaxDynamicSharedMemorySize, SMEM);
        cudaFuncSetAttribute((const void*)gemm_f16<HE_, KSPL, 2>,
                             cudaFuncAttributeMaxDynamicSharedMemorySize, SMEM);
        cudaFuncSetAttribute(attn_logits_kernel,
                             cudaFuncAttributeMaxDynamicSharedMemorySize, LOG_SMEM);
        cudaFuncSetAttribute(attn_av_kernel,
                             cudaFuncAttributeMaxDynamicSharedMemorySize, AV_SMEM);
    }

    // fork stream2: convert wk+wv, then wo, concurrent with main chain
    cudaEventRecord(evFork, 0);
    cudaStreamWaitEvent(s2, evFork, 0);
    cvt_w2_kernel<<<(2 * N8W + 255) / 256, 256, 0, s2>>>(
        (const float4*)Wk, (const float4*)Wv, (uint4*)wqkv);
    cudaEventRecord(evKV, s2);
    cvt_wo_kernel<<<(N8W + 255) / 256, 256, 0, s2>>>(
        (const float4*)Wo, (uint4*)woh);
    cudaEventRecord(evWo, s2);

    // main chain
    cvt_xq_kernel<<<(N8X + N8W + 255) / 256, 256>>>(
        (const float4*)x, (const float4*)Wq, (uint4*)xh, (uint4*)wqkv);

    dim3 gp(HE_ / 128, M_ / 128);   // (64, 16)
    gemm_f16<E_, E_, 0><<<gp, 128, SMEM>>>(xh, wqkv, mask, qh, 0.03125f);

    cudaStreamWaitEvent(0, evKV, 0);
    gemm_f16<E_, E_, 0><<<gp, 128, SMEM>>>(xh, wqkv + (size_t)HE_ * E_,
                                           mask, kh, 1.0f);
    cudaEventRecord(evK2, 0);

    // logits on stream2, concurrent with gemm_v on main
    cudaStreamWaitEvent(s2, evK2, 0);
    attn_logits_kernel<<<dim3(H_, B_), 256, LOG_SMEM, s2>>>(qh, kh, ph);
    cudaEventRecord(evLog, s2);

    gemm_f16<E_, E_, 0><<<gp, 128, SMEM>>>(xh, wqkv + 2 * (size_t)HE_ * E_,
                                           mask, vh, 1.0f);

    cudaStreamWaitEvent(0, evLog, 0);
    attn_av_kernel<<<dim3(H_, B_), 256, AV_SMEM>>>(ph, vh, yh);

    cudaStreamWaitEvent(0, evWo, 0);
    dim3 g2(E_ / 128, M_ / 128, NSPLIT);   // (8, 16, 4) = 512 blocks
    gemm_f16<HE_, KSPL, 2><<<g2, 128, SMEM>>>(yh, woh, mask, part, 1.0f);

    reduce_kernel<<<(M_ * E_ / 4 + 255) / 256, 256>>>(
        (const float4*)part, bo, mask, (float4*)out);
}

// round 15
// speedup vs baseline: 1.1108x; 1.1108x over previous
#include <cuda_runtime.h>
#include <cuda_fp16.h>
#include <cstdint>

#define B_ 32
#define S_ 64
#define H_ 8
#define E_ 1024
#define HE_ 8192
#define M_ 2048
#define NSPLIT 8
#define KSPL (HE_ / NSPLIT)   // 1024

// ---------------- scratch (__device__ globals) ------------------------------
__device__ __half g_qh[B_ * H_ * S_ * E_];
__device__ __half g_kh[B_ * H_ * S_ * E_];
__device__ __half g_vh[B_ * H_ * S_ * E_];
__device__ __half g_y[M_ * HE_];
__device__ __half g_xh[M_ * E_];
__device__ __half g_wqkv[3 * HE_ * E_];
__device__ __half g_woh[E_ * HE_];
__device__ float  g_part[NSPLIT * M_ * E_];

// ---------------- helpers ---------------------------------------------------
__device__ __forceinline__ uint32_t s2u(const void* p) {
    uint32_t a;
    asm("{ .reg .u64 t; cvta.to.shared.u64 t, %1; cvt.u32.u64 %0, t; }"
        : "=r"(a) : "l"(p));
    return a;
}

__device__ __forceinline__ void cpasync16(uint32_t dst, const void* src) {
    asm volatile("cp.async.cg.shared.global [%0], [%1], 16;" :: "r"(dst), "l"(src));
}

__device__ __forceinline__ uint32_t packh2(float a, float b) {
    __half2 h = __floats2half2_rn(a, b);
    return *reinterpret_cast<uint32_t*>(&h);
}

__device__ __forceinline__ void ldmx4(uint32_t* r, uint32_t addr) {
    asm volatile("ldmatrix.sync.aligned.m8n8.x4.shared.b16 {%0,%1,%2,%3}, [%4];"
                 : "=r"(r[0]), "=r"(r[1]), "=r"(r[2]), "=r"(r[3]) : "r"(addr));
}

__device__ __forceinline__ void ldmx4t(uint32_t* r, uint32_t addr) {
    asm volatile("ldmatrix.sync.aligned.m8n8.x4.trans.shared.b16 {%0,%1,%2,%3}, [%4];"
                 : "=r"(r[0]), "=r"(r[1]), "=r"(r[2]), "=r"(r[3]) : "r"(addr));
}

__device__ __forceinline__ void mma_f16(float* d, const uint32_t* a,
                                        const uint32_t* b) {
    asm volatile(
        "mma.sync.aligned.m16n8k16.row.col.f32.f16.f16.f32 "
        "{%0,%1,%2,%3}, {%4,%5,%6,%7}, {%8,%9}, {%0,%1,%2,%3};"
        : "+f"(d[0]), "+f"(d[1]), "+f"(d[2]), "+f"(d[3])
        : "r"(a[0]), "r"(a[1]), "r"(a[2]), "r"(a[3]), "r"(b[0]), "r"(b[1]));
}

// ---------------- fp32->fp16 conversion kernels (32B/thread) ----------------
#define N4X  (M_ * E_ / 4)
#define N4W  (HE_ * E_ / 4)
#define N8X  (N4X / 2)
#define N8W  (N4W / 2)

__global__ void __launch_bounds__(256) cvt_xq_kernel(
    const float4* __restrict__ x, const float4* __restrict__ wq,
    uint4* __restrict__ xh, uint4* __restrict__ wqkvh)
{
    int i = blockIdx.x * blockDim.x + threadIdx.x;
    const float4* src;
    uint4* dst;
    if (i < N8X)            { src = x + i * 2;               dst = xh + i; }
    else if (i < N8X + N8W) { int j = i - N8X; src = wq + j * 2; dst = wqkvh + j; }
    else return;
    float4 v0 = src[0];
    float4 v1 = src[1];
    uint4 o;
    o.x = packh2(v0.x, v0.y);
    o.y = packh2(v0.z, v0.w);
    o.z = packh2(v1.x, v1.y);
    o.w = packh2(v1.z, v1.w);
    *dst = o;
}

__global__ void __launch_bounds__(256) cvt_w2_kernel(
    const float4* __restrict__ wk, const float4* __restrict__ wv,
    uint4* __restrict__ wqkvh)
{
    int i = blockIdx.x * blockDim.x + threadIdx.x;
    const float4* src;
    uint4* dst;
    if (i < N8W)            { src = wk + i * 2;               dst = wqkvh + N8W + i; }
    else if (i < 2 * N8W)   { int j = i - N8W; src = wv + j * 2; dst = wqkvh + 2 * N8W + j; }
    else return;
    float4 v0 = src[0];
    float4 v1 = src[1];
    uint4 o;
    o.x = packh2(v0.x, v0.y);
    o.y = packh2(v0.z, v0.w);
    o.z = packh2(v1.x, v1.y);
    o.w = packh2(v1.z, v1.w);
    *dst = o;
}

__global__ void __launch_bounds__(256) cvt_wo_kernel(
    const float4* __restrict__ wo, uint4* __restrict__ woh)
{
    int i = blockIdx.x * blockDim.x + threadIdx.x;
    if (i >= N8W) return;
    float4 v0 = wo[i * 2];
    float4 v1 = wo[i * 2 + 1];
    uint4 o;
    o.x = packh2(v0.x, v0.y);
    o.y = packh2(v0.z, v0.w);
    o.z = packh2(v1.x, v1.y);
    o.w = packh2(v1.z, v1.w);
    woh[i] = o;
}

// ---------------- fp16 tensor-core GEMM (NT) — R8 config --------------------
// CTA tile 128x128x32, 128 threads, 4 warps (64x64 warp tile), 4-stage
// cp.async, single sync per iter, 64B smem rows, chunk ^= (row>>1)&3.
// MODE 0 (fused QKV, fp16 out): n0 selects {q,k,v}+head; val*mask*scale.
// MODE 2 (split-K partial): fp32 partial into slice blockIdx.z.
#define TSTG 8192
#define NSTAGE 4

template<int KTOT, int KITER, int MODE>
__global__ void __launch_bounds__(128) gemm_f16(
    const __half* __restrict__ A, const __half* __restrict__ Wt,
    const float* __restrict__ mask,
    void* __restrict__ p0, void* __restrict__ p1, void* __restrict__ p2)
{
    constexpr int NIT = KITER / 32;
    extern __shared__ __align__(16) char sm[];
    const uint32_t sAu = s2u(sm);
    const uint32_t sBu = sAu + NSTAGE * TSTG;

    const int tid = threadIdx.x;
    const int wid = tid >> 5, lane = tid & 31;
    const int wm = wid & 1;          // 64-row group
    const int wn = wid >> 1;         // 64-col group
    const int lr = lane >> 2;
    const int lc = lane & 3;
    const int m0 = blockIdx.y * 128;
    const int n0 = blockIdx.x * 128;
    const int k0 = (MODE == 2) ? blockIdx.z * KITER : 0;

    const int ldrow = tid >> 2;      // 0..31
    const int ldch = tid & 3;
    const __half* Abase = A + (size_t)(m0 + ldrow) * KTOT + k0 + ldch * 8;
    const __half* Bbase = Wt + (size_t)(n0 + ldrow) * KTOT + k0 + ldch * 8;

    auto load_stage = [&](int s, int kt) {
#pragma unroll
        for (int p = 0; p < 4; p++) {
            int r = ldrow + p * 32;
            uint32_t doff = (uint32_t)(r * 64 + ((ldch ^ ((r >> 1) & 3)) << 4));
            cpasync16(sAu + s * TSTG + doff, Abase + (size_t)p * 32 * KTOT + kt * 32);
            cpasync16(sBu + s * TSTG + doff, Bbase + (size_t)p * 32 * KTOT + kt * 32);
        }
        asm volatile("cp.async.commit_group;" ::: "memory");
    };

    load_stage(0, 0);
    load_stage(1, 1);
    load_stage(2, 2);

    float acc[4][8][4];              // [mt][nt][frag] = 128 regs
#pragma unroll
    for (int i = 0; i < 4; i++)
#pragma unroll
        for (int j = 0; j < 8; j++)
#pragma unroll
            for (int f = 0; f < 4; f++) acc[i][j][f] = 0.0f;

    const int arow0 = wm * 64 + (lane & 15);
    const int acs = lane >> 4;
    const int midx = lane >> 3;
    const int brow0 = wn * 64 + ((midx >> 1) << 3) + (lane & 7);
    const int bcs = midx & 1;

    for (int j = 0; j < NIT; j++) {
        const int s = j & (NSTAGE - 1);
        if (j < NIT - 2)       asm volatile("cp.async.wait_group 2;" ::: "memory");
        else if (j == NIT - 2) asm volatile("cp.async.wait_group 1;" ::: "memory");
        else                   asm volatile("cp.async.wait_group 0;" ::: "memory");
        __syncthreads();
        if (j + 3 < NIT) load_stage((j + 3) & (NSTAGE - 1), j + 3);

        const uint32_t As = sAu + s * TSTG;
        const uint32_t Bs = sBu + s * TSTG;

#pragma unroll
        for (int ks = 0; ks < 2; ks++) {
            uint32_t bf[4][4];
#pragma unroll
            for (int ntp = 0; ntp < 4; ntp++) {
                int r = brow0 + ntp * 16;
                int ch = (ks * 2 + bcs) ^ ((r >> 1) & 3);
                ldmx4(bf[ntp], Bs + (uint32_t)(r * 64 + (ch << 4)));
            }
#pragma unroll
            for (int mt = 0; mt < 4; mt++) {
                int r = arow0 + mt * 16;
                int ch = (ks * 2 + acs) ^ ((r >> 1) & 3);
                uint32_t af[4];
                ldmx4(af, As + (uint32_t)(r * 64 + (ch << 4)));
#pragma unroll
                for (int nt = 0; nt < 8; nt++)
                    mma_f16(acc[mt][nt], af, bf[nt >> 1] + (nt & 1) * 2);
            }
        }
    }

    // ---- epilogue ----
    __half* outh = nullptr;
    float* outp = nullptr;
    float scale = 1.0f;
    int h = 0, e0 = 0;
    if (MODE == 0) {
        int which = n0 >> 13;
        outh = (__half*)((which == 0) ? p0 : (which == 1) ? p1 : p2);
        if (which == 0) scale = 0.03125f;   // E^-0.5
        h = (n0 >> 10) & 7;
        e0 = n0 & 1023;
    } else {
        outp = (float*)p0 + (size_t)blockIdx.z * M_ * E_;
    }

#pragma unroll
    for (int mt = 0; mt < 4; mt++) {
#pragma unroll
        for (int half = 0; half < 2; half++) {
            const int m = m0 + wm * 64 + mt * 16 + half * 8 + lr;
            const int b = m >> 6;
#pragma unroll
            for (int nt = 0; nt < 8; nt++) {
                const int nrel = wn * 64 + nt * 8 + lc * 2;
                float v0 = acc[mt][nt][half * 2 + 0];
                float v1 = acc[mt][nt][half * 2 + 1];
                if (MODE == 0) {
                    const int e = e0 + nrel;
                    const int sidx = m & 63;
                    const float* mp = mask + (size_t)b * E_ + e;
                    uint32_t o = packh2(v0 * mp[0] * scale, v1 * mp[1] * scale);
                    *(uint32_t*)(outh +
                        ((size_t)((b * H_ + h) * S_ + sidx)) * E_ + e) = o;
                } else {
                    const int n = n0 + nrel;
                    float2 o; o.x = v0; o.y = v1;
                    *(float2*)(outp + (size_t)m * E_ + n) = o;
                }
            }
        }
    }
}

// ---------------- split-K reduce: out = (sum parts + bias) * mask -----------
__global__ void __launch_bounds__(256) reduce_kernel(
    const float4* __restrict__ part, const float* __restrict__ bias,
    const float* __restrict__ mask, float4* __restrict__ out)
{
    const int i = blockIdx.x * blockDim.x + threadIdx.x;
    if (i >= M_ * E_ / 4) return;
    const int idx = i * 4;
    const int m = idx >> 10;
    const int n = idx & 1023;
    const int b = m >> 6;

    float4 s = part[i];
#pragma unroll
    for (int p = 1; p < NSPLIT; p++) {
        float4 t = part[i + (size_t)p * (M_ * E_ / 4)];
        s.x += t.x; s.y += t.y; s.z += t.z; s.w += t.w;
    }

    float4 bv = *(const float4*)(bias + n);
    float4 mv = *(const float4*)(mask + (size_t)b * E_ + n);
    float4 o;
    o.x = (s.x + bv.x) * mv.x;
    o.y = (s.y + bv.y) * mv.y;
    o.z = (s.z + bv.z) * mv.z;
    o.w = (s.w + bv.w) * mv.w;
    out[i] = o;
}

// ---------------- fused attention (one block per (b,h)) ---------------------
#define ATT_SMEM 54272

__global__ void __launch_bounds__(256) attn_fused_kernel(
    const __half* __restrict__ q, const __half* __restrict__ k,
    const __half* __restrict__ v, __half* __restrict__ y)
{
    const int h = blockIdx.x;
    const int b = blockIdx.y;
    const __half* qb = q + (size_t)((b * H_ + h) * S_) * E_;
    const __half* kb = k + (size_t)((b * H_ + h) * S_) * E_;
    const __half* vb = v + (size_t)((b * H_ + h) * S_) * E_;
    __half* yb = y + (size_t)b * S_ * HE_ + h * E_;

    extern __shared__ __align__(16) char sm[];
    const uint32_t sb = s2u(sm);
    const uint32_t sQ[2] = { sb, sb + 9216 };
    const uint32_t sK[2] = { sb + 18432, sb + 27648 };
    float* sL = (float*)(sm + 36864);
    const uint32_t sP = sb;
    const uint32_t sV[2] = { sb + 9216, sb + 26624 };

    const int tid = threadIdx.x;
    const int wid = tid >> 5, lane = tid & 31;
    const int ldr = tid >> 2;
    const int ldc = tid & 3;

    auto loadQK = [&](int s, int kc) {
        const __half* qs = qb + (size_t)ldr * E_ + kc * 64 + ldc * 8;
        const __half* ks = kb + (size_t)ldr * E_ + kc * 64 + ldc * 8;
        uint32_t d = (uint32_t)(ldr * 144 + ldc * 16);
        cpasync16(sQ[s] + d, qs);
        cpasync16(sQ[s] + d + 64, qs + 32);
        cpasync16(sK[s] + d, ks);
        cpasync16(sK[s] + d + 64, ks + 32);
        asm volatile("cp.async.commit_group;" ::: "memory");
    };

    loadQK(0, 0);
    loadQK(1, 1);

    const int wm = wid & 3;
    const int wn = wid >> 2;
    const int arow = wm * 16 + (lane & 15);
    const int acs = lane >> 4;
    const int midx = lane >> 3;
    const int brow = wn * 32 + ((midx >> 1) << 3) + (lane & 7);
    const int bcs = midx & 1;

    float acc[4][4];
#pragma unroll
    for (int i = 0; i < 4; i++)
#pragma unroll
        for (int f = 0; f < 4; f++) acc[i][f] = 0.0f;

    for (int c = 0; c < 16; c++) {
        const int cur = c & 1;
        asm volatile("cp.async.wait_group 1;" ::: "memory");
        __syncthreads();
#pragma unroll
        for (int ks = 0; ks < 4; ks++) {
            uint32_t af[4];
            ldmx4(af, sQ[cur] + (uint32_t)(arow * 144 + ks * 32 + acs * 16));
            uint32_t bf[2][4];
#pragma unroll
            for (int ntp = 0; ntp < 2; ntp++)
                ldmx4(bf[ntp], sK[cur] + (uint32_t)((brow + ntp * 16) * 144 +
                                                    ks * 32 + bcs * 16));
#pragma unroll
            for (int nt = 0; nt < 4; nt++)
                mma_f16(acc[nt], af, bf[nt >> 1] + (nt & 1) * 2);
        }
        __syncthreads();
        if (c + 2 < 16) loadQK(cur, c + 2);
        else asm volatile("cp.async.commit_group;" ::: "memory");
    }

    {
        const int r0 = wm * 16 + (lane >> 2);
        const int cbase = wn * 32 + (lane & 3) * 2;
#pragma unroll
        for (int nt = 0; nt < 4; nt++) {
            sL[(r0)     * 68 + cbase + nt * 8]     = acc[nt][0];
            sL[(r0)     * 68 + cbase + nt * 8 + 1] = acc[nt][1];
            sL[(r0 + 8) * 68 + cbase + nt * 8]     = acc[nt][2];
            sL[(r0 + 8) * 68 + cbase + nt * 8 + 1] = acc[nt][3];
        }
    }
    __syncthreads();

    {
        const int row = tid >> 2;
        const int cb = (tid & 3) * 16;
        float mx = -1e30f;
#pragma unroll
        for (int c = 0; c < 16; c++) mx = fmaxf(mx, sL[row * 68 + cb + c]);
        mx = fmaxf(mx, __shfl_xor_sync(0xffffffffu, mx, 1));
        mx = fmaxf(mx, __shfl_xor_sync(0xffffffffu, mx, 2));
        float ev[16];
        float sum = 0.0f;
#pragma unroll
        for (int c = 0; c < 16; c++) {
            ev[c] = __expf(sL[row * 68 + cb + c] - mx);
            sum += ev[c];
        }
        sum += __shfl_xor_sync(0xffffffffu, sum, 1);
        sum += __shfl_xor_sync(0xffffffffu, sum, 2);
        float inv = 1.0f / sum;
        __syncthreads();
#pragma unroll
        for (int c = 0; c < 8; c++) {
            uint32_t pk = packh2(ev[c * 2] * inv, ev[c * 2 + 1] * inv);
            *(uint32_t*)(sm + (row * 144 + (cb + c * 2) * 2)) = pk;
        }
    }
    __syncthreads();

    auto loadV = [&](int s, int ec) {
        const __half* vs = vb + (size_t)ldr * E_ + ec * 128 + ldc * 8;
        uint32_t d = (uint32_t)(ldr * 272 + ldc * 16);
#pragma unroll
        for (int jj = 0; jj < 4; jj++)
            cpasync16(sV[s] + d + jj * 64, vs + jj * 32);
        asm volatile("cp.async.commit_group;" ::: "memory");
    };

    loadV(0, 0);
    loadV(1, 1);

    const int wm2 = wid & 1;
    const int wn2 = wid >> 1;
    const int prow0 = wm2 * 32 + (lane & 15);
    const int vs0 = ((lane >> 3) & 1) * 8 + (lane & 7);
    const int ve0 = wn2 * 32 + (lane >> 4) * 8;

    for (int ec = 0; ec < 8; ec++) {
        const int cur = ec & 1;
        asm volatile("cp.async.wait_group 1;" ::: "memory");
        __syncthreads();

        float acc2[2][4][4];
#pragma unroll
        for (int i = 0; i < 2; i++)
#pragma unroll
            for (int j = 0; j < 4; j++)
#pragma unroll
                for (int f = 0; f < 4; f++) acc2[i][j][f] = 0.0f;

#pragma unroll
        for (int ks = 0; ks < 4; ks++) {
            uint32_t bf[2][4];
#pragma unroll
            for (int ntp = 0; ntp < 2; ntp++)
                ldmx4t(bf[ntp], sV[cur] + (uint32_t)((ks * 16 + vs0) * 272 +
                                                     (ve0 + ntp * 16) * 2));
#pragma unroll
            for (int mt = 0; mt < 2; mt++) {
                uint32_t af[4];
                ldmx4(af, sP + (uint32_t)((prow0 + mt * 16) * 144 +
                                          ks * 32 + acs * 16));
#pragma unroll
                for (int nt = 0; nt < 4; nt++)
                    mma_f16(acc2[mt][nt], af, bf[nt >> 1] + (nt & 1) * 2);
            }
        }

#pragma unroll
        for (int mt = 0; mt < 2; mt++) {
#pragma unroll
            for (int half = 0; half < 2; half++) {
                const int row = wm2 * 32 + mt * 16 + half * 8 + (lane >> 2);
#pragma unroll
                for (int nt = 0; nt < 4; nt++) {
                    const int col = ec * 128 + wn2 * 32 + nt * 8 + (lane & 3) * 2;
                    uint32_t o = packh2(acc2[mt][nt][half * 2],
                                        acc2[mt][nt][half * 2 + 1]);
                    *(uint32_t*)(yb + (size_t)row * HE_ + col) = o;
                }
            }
        }

        __syncthreads();
        if (ec + 2 < 8) loadV(cur, ec + 2);
        else asm volatile("cp.async.commit_group;" ::: "memory");
    }
}

// ---------------------------------------------------------------------------
extern "C" void kernel_launch(void* const* d_in, const int* in_sizes, int n_in,
                              void* d_out, int out_size)
{
    const float* x    = (const float*)d_in[0];
    const float* mask = (const float*)d_in[1];
    const float* Wq   = (const float*)d_in[2];
    const float* Wk   = (const float*)d_in[3];
    const float* Wv   = (const float*)d_in[4];
    const float* Wo   = (const float*)d_in[5];
    const float* bo   = (const float*)d_in[6];
    float* out = (float*)d_out;

    __half *qh, *kh, *vh, *yh, *xh, *wqkv, *woh;
    float *part;
    cudaGetSymbolAddress((void**)&qh, g_qh);
    cudaGetSymbolAddress((void**)&kh, g_kh);
    cudaGetSymbolAddress((void**)&vh, g_vh);
    cudaGetSymbolAddress((void**)&yh, g_y);
    cudaGetSymbolAddress((void**)&xh, g_xh);
    cudaGetSymbolAddress((void**)&wqkv, g_wqkv);
    cudaGetSymbolAddress((void**)&woh, g_woh);
    cudaGetSymbolAddress((void**)&part, g_part);

    const int SMEM = 2 * NSTAGE * TSTG;   // 65536
    static cudaStream_t s2 = nullptr;
    static cudaEvent_t evFork = nullptr, evKV = nullptr, evWo = nullptr;
    if (s2 == nullptr) {
        // first call is the uncaptured correctness run: safe to create here
        cudaStreamCreateWithFlags(&s2, cudaStreamNonBlocking);
        cudaEventCreateWithFlags(&evFork, cudaEventDisableTiming);
        cudaEventCreateWithFlags(&evKV, cudaEventDisableTiming);
        cudaEventCreateWithFlags(&evWo, cudaEventDisableTiming);
        cudaFuncSetAttribute((const void*)gemm_f16<E_, E_, 0>,
                             cudaFuncAttributeMaxDynamicSharedMemorySize, SMEM);
        cudaFuncSetAttribute((const void*)gemm_f16<HE_, KSPL, 2>,
                             cudaFuncAttributeMaxDynamicSharedMemorySize, SMEM);
        cudaFuncSetAttribute(attn_fused_kernel,
                             cudaFuncAttributeMaxDynamicSharedMemorySize, ATT_SMEM);
    }

    // fork stream2: wk+wv (gates QKV GEMM), then wo (gates out-GEMM)
    cudaEventRecord(evFork, 0);
    cudaStreamWaitEvent(s2, evFork, 0);
    cvt_w2_kernel<<<(2 * N8W + 255) / 256, 256, 0, s2>>>(
        (const float4*)Wk, (const float4*)Wv, (uint4*)wqkv);
    cudaEventRecord(evKV, s2);
    cvt_wo_kernel<<<(N8W + 255) / 256, 256, 0, s2>>>(
        (const float4*)Wo, (uint4*)woh);
    cudaEventRecord(evWo, s2);

    // main chain: convert x+wq only, then fused QKV (needs wk/wv -> wait evKV)
    cvt_xq_kernel<<<(N8X + N8W + 255) / 256, 256>>>(
        (const float4*)x, (const float4*)Wq, (uint4*)xh, (uint4*)wqkv);

    cudaStreamWaitEvent(0, evKV, 0);
    dim3 g1(3 * HE_ / 128, M_ / 128);   // (192, 16) = 3072 blocks
    gemm_f16<E_, E_, 0><<<g1, 128, SMEM>>>(xh, wqkv, mask, qh, kh, vh);

    attn_fused_kernel<<<dim3(H_, B_), 256, ATT_SMEM>>>(qh, kh, vh, yh);

    cudaStreamWaitEvent(0, evWo, 0);
    dim3 g2(E_ / 128, M_ / 128, NSPLIT);   // (8, 16, 8) = 1024 blocks
    gemm_f16<HE_, KSPL, 2><<<g2, 128, SMEM>>>(yh, woh, mask, part, nullptr, nullptr);

    reduce_kernel<<<(M_ * E_ / 4 + 255) / 256, 256>>>(
        (const float4*)part, bo, mask, (float4*)out);
}

// round 16
// speedup vs baseline: 1.1323x; 1.0194x over previous
#include <cuda_runtime.h>
#include <cuda_fp16.h>
#include <cstdint>

#define B_ 32
#define S_ 64
#define H_ 8
#define E_ 1024
#define HE_ 8192
#define M_ 2048
#define NSPLIT 4
#define KSPL (HE_ / NSPLIT)   // 2048

// ---------------- scratch (__device__ globals) ------------------------------
__device__ __half g_qh[B_ * H_ * S_ * E_];
__device__ __half g_kh[B_ * H_ * S_ * E_];
__device__ __half g_vh[B_ * H_ * S_ * E_];
__device__ __half g_y[M_ * HE_];
__device__ __half g_xh[M_ * E_];
__device__ __half g_wqkv[3 * HE_ * E_];
__device__ __half g_woh[E_ * HE_];
__device__ float  g_part[NSPLIT * M_ * E_];

// ---------------- helpers ---------------------------------------------------
__device__ __forceinline__ uint32_t s2u(const void* p) {
    uint32_t a;
    asm("{ .reg .u64 t; cvta.to.shared.u64 t, %1; cvt.u32.u64 %0, t; }"
        : "=r"(a) : "l"(p));
    return a;
}

__device__ __forceinline__ void cpasync16(uint32_t dst, const void* src) {
    asm volatile("cp.async.cg.shared.global [%0], [%1], 16;" :: "r"(dst), "l"(src));
}

__device__ __forceinline__ uint32_t packh2(float a, float b) {
    __half2 h = __floats2half2_rn(a, b);
    return *reinterpret_cast<uint32_t*>(&h);
}

__device__ __forceinline__ void ldmx4(uint32_t* r, uint32_t addr) {
    asm volatile("ldmatrix.sync.aligned.m8n8.x4.shared.b16 {%0,%1,%2,%3}, [%4];"
                 : "=r"(r[0]), "=r"(r[1]), "=r"(r[2]), "=r"(r[3]) : "r"(addr));
}

__device__ __forceinline__ void ldmx4t(uint32_t* r, uint32_t addr) {
    asm volatile("ldmatrix.sync.aligned.m8n8.x4.trans.shared.b16 {%0,%1,%2,%3}, [%4];"
                 : "=r"(r[0]), "=r"(r[1]), "=r"(r[2]), "=r"(r[3]) : "r"(addr));
}

__device__ __forceinline__ void mma_f16(float* d, const uint32_t* a,
                                        const uint32_t* b) {
    asm volatile(
        "mma.sync.aligned.m16n8k16.row.col.f32.f16.f16.f32 "
        "{%0,%1,%2,%3}, {%4,%5,%6,%7}, {%8,%9}, {%0,%1,%2,%3};"
        : "+f"(d[0]), "+f"(d[1]), "+f"(d[2]), "+f"(d[3])
        : "r"(a[0]), "r"(a[1]), "r"(a[2]), "r"(a[3]), "r"(b[0]), "r"(b[1]));
}

// ---------------- fp32->fp16 conversion kernels (32B/thread) ----------------
#define N4X  (M_ * E_ / 4)
#define N4W  (HE_ * E_ / 4)
#define N8X  (N4X / 2)
#define N8W  (N4W / 2)

__global__ void __launch_bounds__(256) cvt_xq_kernel(
    const float4* __restrict__ x, const float4* __restrict__ wq,
    uint4* __restrict__ xh, uint4* __restrict__ wqkvh)
{
    int i = blockIdx.x * blockDim.x + threadIdx.x;
    const float4* src;
    uint4* dst;
    if (i < N8X)            { src = x + i * 2;               dst = xh + i; }
    else if (i < N8X + N8W) { int j = i - N8X; src = wq + j * 2; dst = wqkvh + j; }
    else return;
    float4 v0 = src[0];
    float4 v1 = src[1];
    uint4 o;
    o.x = packh2(v0.x, v0.y);
    o.y = packh2(v0.z, v0.w);
    o.z = packh2(v1.x, v1.y);
    o.w = packh2(v1.z, v1.w);
    *dst = o;
}

__global__ void __launch_bounds__(256) cvt_w2_kernel(
    const float4* __restrict__ wk, const float4* __restrict__ wv,
    uint4* __restrict__ wqkvh)
{
    int i = blockIdx.x * blockDim.x + threadIdx.x;
    const float4* src;
    uint4* dst;
    if (i < N8W)            { src = wk + i * 2;               dst = wqkvh + N8W + i; }
    else if (i < 2 * N8W)   { int j = i - N8W; src = wv + j * 2; dst = wqkvh + 2 * N8W + j; }
    else return;
    float4 v0 = src[0];
    float4 v1 = src[1];
    uint4 o;
    o.x = packh2(v0.x, v0.y);
    o.y = packh2(v0.z, v0.w);
    o.z = packh2(v1.x, v1.y);
    o.w = packh2(v1.z, v1.w);
    *dst = o;
}

__global__ void __launch_bounds__(256) cvt_wo_kernel(
    const float4* __restrict__ wo, uint4* __restrict__ woh)
{
    int i = blockIdx.x * blockDim.x + threadIdx.x;
    if (i >= N8W) return;
    float4 v0 = wo[i * 2];
    float4 v1 = wo[i * 2 + 1];
    uint4 o;
    o.x = packh2(v0.x, v0.y);
    o.y = packh2(v0.z, v0.w);
    o.z = packh2(v1.x, v1.y);
    o.w = packh2(v1.z, v1.w);
    woh[i] = o;
}

// ---------------- fp16 tensor-core GEMM (NT) — R8 config --------------------
// CTA tile 128x128x32, 128 threads, 4 warps (64x64 warp tile), 4-stage
// cp.async, single sync per iter, 64B smem rows, chunk ^= (row>>1)&3.
// MODE 0 (fused QKV, fp16 out): n0 selects {q,k,v}+head; val*mask*scale.
// MODE 2 (split-K partial): fp32 partial into slice blockIdx.z.
#define TSTG 8192
#define NSTAGE 4

template<int KTOT, int KITER, int MODE>
__global__ void __launch_bounds__(128) gemm_f16(
    const __half* __restrict__ A, const __half* __restrict__ Wt,
    const float* __restrict__ mask,
    void* __restrict__ p0, void* __restrict__ p1, void* __restrict__ p2)
{
    constexpr int NIT = KITER / 32;
    extern __shared__ __align__(16) char sm[];
    const uint32_t sAu = s2u(sm);
    const uint32_t sBu = sAu + NSTAGE * TSTG;

    const int tid = threadIdx.x;
    const int wid = tid >> 5, lane = tid & 31;
    const int wm = wid & 1;          // 64-row group
    const int wn = wid >> 1;         // 64-col group
    const int lr = lane >> 2;
    const int lc = lane & 3;
    const int m0 = blockIdx.y * 128;
    const int n0 = blockIdx.x * 128;
    const int k0 = (MODE == 2) ? blockIdx.z * KITER : 0;

    const int ldrow = tid >> 2;      // 0..31
    const int ldch = tid & 3;
    const __half* Abase = A + (size_t)(m0 + ldrow) * KTOT + k0 + ldch * 8;
    const __half* Bbase = Wt + (size_t)(n0 + ldrow) * KTOT + k0 + ldch * 8;

    auto load_stage = [&](int s, int kt) {
#pragma unroll
        for (int p = 0; p < 4; p++) {
            int r = ldrow + p * 32;
            uint32_t doff = (uint32_t)(r * 64 + ((ldch ^ ((r >> 1) & 3)) << 4));
            cpasync16(sAu + s * TSTG + doff, Abase + (size_t)p * 32 * KTOT + kt * 32);
            cpasync16(sBu + s * TSTG + doff, Bbase + (size_t)p * 32 * KTOT + kt * 32);
        }
        asm volatile("cp.async.commit_group;" ::: "memory");
    };

    load_stage(0, 0);
    load_stage(1, 1);
    load_stage(2, 2);

    float acc[4][8][4];              // [mt][nt][frag] = 128 regs
#pragma unroll
    for (int i = 0; i < 4; i++)
#pragma unroll
        for (int j = 0; j < 8; j++)
#pragma unroll
            for (int f = 0; f < 4; f++) acc[i][j][f] = 0.0f;

    const int arow0 = wm * 64 + (lane & 15);
    const int acs = lane >> 4;
    const int midx = lane >> 3;
    const int brow0 = wn * 64 + ((midx >> 1) << 3) + (lane & 7);
    const int bcs = midx & 1;

    for (int j = 0; j < NIT; j++) {
        const int s = j & (NSTAGE - 1);
        if (j < NIT - 2)       asm volatile("cp.async.wait_group 2;" ::: "memory");
        else if (j == NIT - 2) asm volatile("cp.async.wait_group 1;" ::: "memory");
        else                   asm volatile("cp.async.wait_group 0;" ::: "memory");
        __syncthreads();
        if (j + 3 < NIT) load_stage((j + 3) & (NSTAGE - 1), j + 3);

        const uint32_t As = sAu + s * TSTG;
        const uint32_t Bs = sBu + s * TSTG;

#pragma unroll
        for (int ks = 0; ks < 2; ks++) {
            uint32_t bf[4][4];
#pragma unroll
            for (int ntp = 0; ntp < 4; ntp++) {
                int r = brow0 + ntp * 16;
                int ch = (ks * 2 + bcs) ^ ((r >> 1) & 3);
                ldmx4(bf[ntp], Bs + (uint32_t)(r * 64 + (ch << 4)));
            }
#pragma unroll
            for (int mt = 0; mt < 4; mt++) {
                int r = arow0 + mt * 16;
                int ch = (ks * 2 + acs) ^ ((r >> 1) & 3);
                uint32_t af[4];
                ldmx4(af, As + (uint32_t)(r * 64 + (ch << 4)));
#pragma unroll
                for (int nt = 0; nt < 8; nt++)
                    mma_f16(acc[mt][nt], af, bf[nt >> 1] + (nt & 1) * 2);
            }
        }
    }

    // ---- epilogue ----
    __half* outh = nullptr;
    float* outp = nullptr;
    float scale = 1.0f;
    int h = 0, e0 = 0;
    if (MODE == 0) {
        int which = n0 >> 13;
        outh = (__half*)((which == 0) ? p0 : (which == 1) ? p1 : p2);
        if (which == 0) scale = 0.03125f;   // E^-0.5
        h = (n0 >> 10) & 7;
        e0 = n0 & 1023;
    } else {
        outp = (float*)p0 + (size_t)blockIdx.z * M_ * E_;
    }

#pragma unroll
    for (int mt = 0; mt < 4; mt++) {
#pragma unroll
        for (int half = 0; half < 2; half++) {
            const int m = m0 + wm * 64 + mt * 16 + half * 8 + lr;
            const int b = m >> 6;
#pragma unroll
            for (int nt = 0; nt < 8; nt++) {
                const int nrel = wn * 64 + nt * 8 + lc * 2;
                float v0 = acc[mt][nt][half * 2 + 0];
                float v1 = acc[mt][nt][half * 2 + 1];
                if (MODE == 0) {
                    const int e = e0 + nrel;
                    const int sidx = m & 63;
                    const float* mp = mask + (size_t)b * E_ + e;
                    uint32_t o = packh2(v0 * mp[0] * scale, v1 * mp[1] * scale);
                    *(uint32_t*)(outh +
                        ((size_t)((b * H_ + h) * S_ + sidx)) * E_ + e) = o;
                } else {
                    const int n = n0 + nrel;
                    float2 o; o.x = v0; o.y = v1;
                    *(float2*)(outp + (size_t)m * E_ + n) = o;
                }
            }
        }
    }
}

// ---------------- split-K reduce: out = (sum parts + bias) * mask -----------
__global__ void __launch_bounds__(256) reduce_kernel(
    const float4* __restrict__ part, const float* __restrict__ bias,
    const float* __restrict__ mask, float4* __restrict__ out)
{
    const int i = blockIdx.x * blockDim.x + threadIdx.x;
    if (i >= M_ * E_ / 4) return;
    const int idx = i * 4;
    const int m = idx >> 10;
    const int n = idx & 1023;
    const int b = m >> 6;

    float4 s = part[i];
#pragma unroll
    for (int p = 1; p < NSPLIT; p++) {
        float4 t = part[i + (size_t)p * (M_ * E_ / 4)];
        s.x += t.x; s.y += t.y; s.z += t.z; s.w += t.w;
    }

    float4 bv = *(const float4*)(bias + n);
    float4 mv = *(const float4*)(mask + (size_t)b * E_ + n);
    float4 o;
    o.x = (s.x + bv.x) * mv.x;
    o.y = (s.y + bv.y) * mv.y;
    o.z = (s.z + bv.z) * mv.z;
    o.w = (s.w + bv.w) * mv.w;
    out[i] = o;
}

// ---------------- fused attention (one block per (b,h)) ---------------------
#define ATT_SMEM 54272

__global__ void __launch_bounds__(256) attn_fused_kernel(
    const __half* __restrict__ q, const __half* __restrict__ k,
    const __half* __restrict__ v, __half* __restrict__ y)
{
    const int h = blockIdx.x;
    const int b = blockIdx.y;
    const __half* qb = q + (size_t)((b * H_ + h) * S_) * E_;
    const __half* kb = k + (size_t)((b * H_ + h) * S_) * E_;
    const __half* vb = v + (size_t)((b * H_ + h) * S_) * E_;
    __half* yb = y + (size_t)b * S_ * HE_ + h * E_;

    extern __shared__ __align__(16) char sm[];
    const uint32_t sb = s2u(sm);
    const uint32_t sQ[2] = { sb, sb + 9216 };
    const uint32_t sK[2] = { sb + 18432, sb + 27648 };
    float* sL = (float*)(sm + 36864);
    const uint32_t sP = sb;
    const uint32_t sV[2] = { sb + 9216, sb + 26624 };

    const int tid = threadIdx.x;
    const int wid = tid >> 5, lane = tid & 31;
    const int ldr = tid >> 2;
    const int ldc = tid & 3;

    auto loadQK = [&](int s, int kc) {
        const __half* qs = qb + (size_t)ldr * E_ + kc * 64 + ldc * 8;
        const __half* ks = kb + (size_t)ldr * E_ + kc * 64 + ldc * 8;
        uint32_t d = (uint32_t)(ldr * 144 + ldc * 16);
        cpasync16(sQ[s] + d, qs);
        cpasync16(sQ[s] + d + 64, qs + 32);
        cpasync16(sK[s] + d, ks);
        cpasync16(sK[s] + d + 64, ks + 32);
        asm volatile("cp.async.commit_group;" ::: "memory");
    };

    loadQK(0, 0);
    loadQK(1, 1);

    const int wm = wid & 3;
    const int wn = wid >> 2;
    const int arow = wm * 16 + (lane & 15);
    const int acs = lane >> 4;
    const int midx = lane >> 3;
    const int brow = wn * 32 + ((midx >> 1) << 3) + (lane & 7);
    const int bcs = midx & 1;

    float acc[4][4];
#pragma unroll
    for (int i = 0; i < 4; i++)
#pragma unroll
        for (int f = 0; f < 4; f++) acc[i][f] = 0.0f;

    for (int c = 0; c < 16; c++) {
        const int cur = c & 1;
        asm volatile("cp.async.wait_group 1;" ::: "memory");
        __syncthreads();
#pragma unroll
        for (int ks = 0; ks < 4; ks++) {
            uint32_t af[4];
            ldmx4(af, sQ[cur] + (uint32_t)(arow * 144 + ks * 32 + acs * 16));
            uint32_t bf[2][4];
#pragma unroll
            for (int ntp = 0; ntp < 2; ntp++)
                ldmx4(bf[ntp], sK[cur] + (uint32_t)((brow + ntp * 16) * 144 +
                                                    ks * 32 + bcs * 16));
#pragma unroll
            for (int nt = 0; nt < 4; nt++)
                mma_f16(acc[nt], af, bf[nt >> 1] + (nt & 1) * 2);
        }
        __syncthreads();
        if (c + 2 < 16) loadQK(cur, c + 2);
        else asm volatile("cp.async.commit_group;" ::: "memory");
    }

    {
        const int r0 = wm * 16 + (lane >> 2);
        const int cbase = wn * 32 + (lane & 3) * 2;
#pragma unroll
        for (int nt = 0; nt < 4; nt++) {
            sL[(r0)     * 68 + cbase + nt * 8]     = acc[nt][0];
            sL[(r0)     * 68 + cbase + nt * 8 + 1] = acc[nt][1];
            sL[(r0 + 8) * 68 + cbase + nt * 8]     = acc[nt][2];
            sL[(r0 + 8) * 68 + cbase + nt * 8 + 1] = acc[nt][3];
        }
    }
    __syncthreads();

    {
        const int row = tid >> 2;
        const int cb = (tid & 3) * 16;
        float mx = -1e30f;
#pragma unroll
        for (int c = 0; c < 16; c++) mx = fmaxf(mx, sL[row * 68 + cb + c]);
        mx = fmaxf(mx, __shfl_xor_sync(0xffffffffu, mx, 1));
        mx = fmaxf(mx, __shfl_xor_sync(0xffffffffu, mx, 2));
        float ev[16];
        float sum = 0.0f;
#pragma unroll
        for (int c = 0; c < 16; c++) {
            ev[c] = __expf(sL[row * 68 + cb + c] - mx);
            sum += ev[c];
        }
        sum += __shfl_xor_sync(0xffffffffu, sum, 1);
        sum += __shfl_xor_sync(0xffffffffu, sum, 2);
        float inv = 1.0f / sum;
        __syncthreads();
#pragma unroll
        for (int c = 0; c < 8; c++) {
            uint32_t pk = packh2(ev[c * 2] * inv, ev[c * 2 + 1] * inv);
            *(uint32_t*)(sm + (row * 144 + (cb + c * 2) * 2)) = pk;
        }
    }
    __syncthreads();

    auto loadV = [&](int s, int ec) {
        const __half* vs = vb + (size_t)ldr * E_ + ec * 128 + ldc * 8;
        uint32_t d = (uint32_t)(ldr * 272 + ldc * 16);
#pragma unroll
        for (int jj = 0; jj < 4; jj++)
            cpasync16(sV[s] + d + jj * 64, vs + jj * 32);
        asm volatile("cp.async.commit_group;" ::: "memory");
    };

    loadV(0, 0);
    loadV(1, 1);

    const int wm2 = wid & 1;
    const int wn2 = wid >> 1;
    const int prow0 = wm2 * 32 + (lane & 15);
    const int vs0 = ((lane >> 3) & 1) * 8 + (lane & 7);
    const int ve0 = wn2 * 32 + (lane >> 4) * 8;

    for (int ec = 0; ec < 8; ec++) {
        const int cur = ec & 1;
        asm volatile("cp.async.wait_group 1;" ::: "memory");
        __syncthreads();

        float acc2[2][4][4];
#pragma unroll
        for (int i = 0; i < 2; i++)
#pragma unroll
            for (int j = 0; j < 4; j++)
#pragma unroll
                for (int f = 0; f < 4; f++) acc2[i][j][f] = 0.0f;

#pragma unroll
        for (int ks = 0; ks < 4; ks++) {
            uint32_t bf[2][4];
#pragma unroll
            for (int ntp = 0; ntp < 2; ntp++)
                ldmx4t(bf[ntp], sV[cur] + (uint32_t)((ks * 16 + vs0) * 272 +
                                                     (ve0 + ntp * 16) * 2));
#pragma unroll
            for (int mt = 0; mt < 2; mt++) {
                uint32_t af[4];
                ldmx4(af, sP + (uint32_t)((prow0 + mt * 16) * 144 +
                                          ks * 32 + acs * 16));
#pragma unroll
                for (int nt = 0; nt < 4; nt++)
                    mma_f16(acc2[mt][nt], af, bf[nt >> 1] + (nt & 1) * 2);
            }
        }

#pragma unroll
        for (int mt = 0; mt < 2; mt++) {
#pragma unroll
            for (int half = 0; half < 2; half++) {
                const int row = wm2 * 32 + mt * 16 + half * 8 + (lane >> 2);
#pragma unroll
                for (int nt = 0; nt < 4; nt++) {
                    const int col = ec * 128 + wn2 * 32 + nt * 8 + (lane & 3) * 2;
                    uint32_t o = packh2(acc2[mt][nt][half * 2],
                                        acc2[mt][nt][half * 2 + 1]);
                    *(uint32_t*)(yb + (size_t)row * HE_ + col) = o;
                }
            }
        }

        __syncthreads();
        if (ec + 2 < 8) loadV(cur, ec + 2);
        else asm volatile("cp.async.commit_group;" ::: "memory");
    }
}

// ---------------------------------------------------------------------------
extern "C" void kernel_launch(void* const* d_in, const int* in_sizes, int n_in,
                              void* d_out, int out_size)
{
    const float* x    = (const float*)d_in[0];
    const float* mask = (const float*)d_in[1];
    const float* Wq   = (const float*)d_in[2];
    const float* Wk   = (const float*)d_in[3];
    const float* Wv   = (const float*)d_in[4];
    const float* Wo   = (const float*)d_in[5];
    const float* bo   = (const float*)d_in[6];
    float* out = (float*)d_out;

    __half *qh, *kh, *vh, *yh, *xh, *wqkv, *woh;
    float *part;
    cudaGetSymbolAddress((void**)&qh, g_qh);
    cudaGetSymbolAddress((void**)&kh, g_kh);
    cudaGetSymbolAddress((void**)&vh, g_vh);
    cudaGetSymbolAddress((void**)&yh, g_y);
    cudaGetSymbolAddress((void**)&xh, g_xh);
    cudaGetSymbolAddress((void**)&wqkv, g_wqkv);
    cudaGetSymbolAddress((void**)&woh, g_woh);
    cudaGetSymbolAddress((void**)&part, g_part);

    const int SMEM = 2 * NSTAGE * TSTG;   // 65536
    static cudaStream_t s2 = nullptr;
    static cudaEvent_t evFork = nullptr, evKV = nullptr, evWo = nullptr;
    if (s2 == nullptr) {
        // first call is the uncaptured correctness run: safe to create here
        cudaStreamCreateWithFlags(&s2, cudaStreamNonBlocking);
        cudaEventCreateWithFlags(&evFork, cudaEventDisableTiming);
        cudaEventCreateWithFlags(&evKV, cudaEventDisableTiming);
        cudaEventCreateWithFlags(&evWo, cudaEventDisableTiming);
        cudaFuncSetAttribute((const void*)gemm_f16<E_, E_, 0>,
                             cudaFuncAttributeMaxDynamicSharedMemorySize, SMEM);
        cudaFuncSetAttribute((const void*)gemm_f16<HE_, KSPL, 2>,
                             cudaFuncAttributeMaxDynamicSharedMemorySize, SMEM);
        cudaFuncSetAttribute(attn_fused_kernel,
                             cudaFuncAttributeMaxDynamicSharedMemorySize, ATT_SMEM);
    }

    // fork stream2: wk+wv (gates QKV GEMM), then wo (gates out-GEMM)
    cudaEventRecord(evFork, 0);
    cudaStreamWaitEvent(s2, evFork, 0);
    cvt_w2_kernel<<<(2 * N8W + 255) / 256, 256, 0, s2>>>(
        (const float4*)Wk, (const float4*)Wv, (uint4*)wqkv);
    cudaEventRecord(evKV, s2);
    cvt_wo_kernel<<<(N8W + 255) / 256, 256, 0, s2>>>(
        (const float4*)Wo, (uint4*)woh);
    cudaEventRecord(evWo, s2);

    // main chain: convert x+wq only, then fused QKV (needs wk/wv -> wait evKV)
    cvt_xq_kernel<<<(N8X + N8W + 255) / 256, 256>>>(
        (const float4*)x, (const float4*)Wq, (uint4*)xh, (uint4*)wqkv);

    cudaStreamWaitEvent(0, evKV, 0);
    dim3 g1(3 * HE_ / 128, M_ / 128);   // (192, 16) = 3072 blocks
    gemm_f16<E_, E_, 0><<<g1, 128, SMEM>>>(xh, wqkv, mask, qh, kh, vh);

    attn_fused_kernel<<<dim3(H_, B_), 256, ATT_SMEM>>>(qh, kh, vh, yh);

    cudaStreamWaitEvent(0, evWo, 0);
    dim3 g2(E_ / 128, M_ / 128, NSPLIT);   // (8, 16, 4) = 512 blocks
    gemm_f16<HE_, KSPL, 2><<<g2, 128, SMEM>>>(yh, woh, mask, part, nullptr, nullptr);

    reduce_kernel<<<(M_ * E_ / 4 + 255) / 256, 256>>>(
        (const float4*)part, bo, mask, (float4*)out);
}